// round 5
// baseline (speedup 1.0000x reference)
#include <cuda_runtime.h>

// Shapes fixed by the problem's setup_inputs().
#define B_  8
#define H_  16
#define NT_ 512
#define NV_ 576

#define EPS_MIN 1e-8f
#define EPS_MAX 1.0f

#define NBLK (18 * 16 * 16)   // grid size of diag_kernel = 4608

// Per-layer diagonal accumulators (atomic float adds).
// Zero-initialized at module load; the fused finalize (last block) re-zeroes
// them after each use, so every kernel_launch call starts from zeros.
__device__ float g_tdiag[2 * B_ * NT_];   // 8192 floats
__device__ float g_vdiag[2 * B_ * NV_];   // 9216 floats

// Last-block ticket (atomicInc with modulus NBLK-1 wraps back to 0).
__device__ unsigned int g_ticket;

// One block (256 threads) = 32(i) x 32(j) tile for one (layer, b).
//   thread t: p = t & 7 (float4 slot), q = t >> 3 (row index 0..31)
//   attn_t: element (i = i0+q, j = j0+4p..+3)  -> float4 along j (contiguous)
//   attn_v: element (j = j0+q, i = i0+4p..+3)  -> float4 along i (contiguous)
// prod[i][j] = P_t_sum[i][j] * P_v_sum[j][i]; row sums -> g_tdiag,
// column sums -> g_vdiag. The LAST block to finish performs the scalar
// -log/clip reduction and writes d_out (threadFenceReduction pattern).
__global__ __launch_bounds__(256)
void diag_kernel(const float* __restrict__ at0, const float* __restrict__ av0,
                 const float* __restrict__ at1, const float* __restrict__ av1,
                 float* __restrict__ out) {
    __shared__ float shV[32][33];   // P_v sums, stride-33 -> conflict-free transpose
    __shared__ float shP[32][33];   // prod tile for column reduction
    __shared__ bool  is_last;

    const int t = threadIdx.x;
    const int p = t & 7;            // float4 slot within row
    const int q = t >> 3;           // row (i for attn_t, j for attn_v)

    const int z     = blockIdx.z;
    const int layer = z >> 3;
    const int b     = z & 7;
    const int i0    = blockIdx.y * 32;
    const int j0    = blockIdx.x * 32;

    const float* __restrict__ at = layer ? at1 : at0;
    const float* __restrict__ av = layer ? av1 : av0;

    // Base pointers at h = 0; head stride in float4 units.
    const size_t hstride4 = (size_t)NT_ * NV_ / 4;   // 73728
    const float4* __restrict__ pt = (const float4*)(
        at + (((size_t)b * H_) * NT_ + (i0 + q)) * NV_ + (j0 + 4 * p));
    const float4* __restrict__ pv = (const float4*)(
        av + (((size_t)b * H_) * NV_ + (j0 + q)) * NT_ + (i0 + 4 * p));

    float4 st = make_float4(0.f, 0.f, 0.f, 0.f);
    float4 sv = make_float4(0.f, 0.f, 0.f, 0.f);
#pragma unroll
    for (int h = 0; h < H_; ++h) {
        const float4 a = pt[h * hstride4];   // default cached loads: this was
        const float4 v = pv[h * hstride4];   // the 6.9 TB/s configuration
        st.x += a.x; st.y += a.y; st.z += a.z; st.w += a.w;
        sv.x += v.x; sv.y += v.y; sv.z += v.z; sv.w += v.w;
    }

    // Stage P_v sums: shV[j - j0][i - i0]
    shV[q][4 * p + 0] = sv.x;
    shV[q][4 * p + 1] = sv.y;
    shV[q][4 * p + 2] = sv.z;
    shV[q][4 * p + 3] = sv.w;
    __syncthreads();

    // prod for (i = i0+q, j = j0+4p+c): needs shV[4p+c][q] (conflict-free).
    const float pr0 = st.x * shV[4 * p + 0][q];
    const float pr1 = st.y * shV[4 * p + 1][q];
    const float pr2 = st.z * shV[4 * p + 2][q];
    const float pr3 = st.w * shV[4 * p + 3][q];

    // Row sum over j: reduce the 8 threads (p = 0..7) sharing row q.
    float rs = (pr0 + pr1) + (pr2 + pr3);
    rs += __shfl_xor_sync(0xffffffffu, rs, 1);
    rs += __shfl_xor_sync(0xffffffffu, rs, 2);
    rs += __shfl_xor_sync(0xffffffffu, rs, 4);
    if (p == 0)
        atomicAdd(&g_tdiag[layer * (B_ * NT_) + b * NT_ + i0 + q], rs);

    // Column sums: stage prod tile, then read transposed.
    shP[q][4 * p + 0] = pr0;
    shP[q][4 * p + 1] = pr1;
    shP[q][4 * p + 2] = pr2;
    shP[q][4 * p + 3] = pr3;
    __syncthreads();

    // Thread handles column j = j0+q, rows i = 4p+c (conflict-free reads).
    float cs = shP[4 * p + 0][q] + shP[4 * p + 1][q]
             + shP[4 * p + 2][q] + shP[4 * p + 3][q];
    cs += __shfl_xor_sync(0xffffffffu, cs, 1);
    cs += __shfl_xor_sync(0xffffffffu, cs, 2);
    cs += __shfl_xor_sync(0xffffffffu, cs, 4);
    if (p == 0)
        atomicAdd(&g_vdiag[layer * (B_ * NV_) + b * NV_ + j0 + q], cs);

    // ---- last-block fused finalize (threadFenceReduction pattern) ----
    // Producers: make this block's atomics globally visible, then take a ticket.
    if (p == 0) __threadfence();     // every thread that issued an atomic fences
    __syncthreads();
    if (t == 0) {
        unsigned int ticket = atomicInc(&g_ticket, NBLK - 1);
        is_last = (ticket == NBLK - 1);
    }
    __syncthreads();
    if (!is_last) return;

    // Consumer side: acquire all blocks' atomic results.
    __threadfence();

    const float inv_h2 = 1.0f / (float)(H_ * H_);  // sums -> products of means
    float acc_t = 0.0f, acc_v = 0.0f;
    for (int idx = t; idx < 2 * B_ * NT_; idx += 256) {
        float d = __ldcg(&g_tdiag[idx]) * inv_h2;   // L2-coherent load
        g_tdiag[idx] = 0.0f;                        // reset for next replay
        d = fminf(fmaxf(d, EPS_MIN), EPS_MAX);
        acc_t -= __logf(d);
    }
    for (int idx = t; idx < 2 * B_ * NV_; idx += 256) {
        float d = __ldcg(&g_vdiag[idx]) * inv_h2;
        g_vdiag[idx] = 0.0f;
        d = fminf(fmaxf(d, EPS_MIN), EPS_MAX);
        acc_v -= __logf(d);
    }

    // Intra-block reduction of (acc_t, acc_v). Reuse shV storage.
#pragma unroll
    for (int o = 16; o > 0; o >>= 1) {
        acc_t += __shfl_xor_sync(0xffffffffu, acc_t, o);
        acc_v += __shfl_xor_sync(0xffffffffu, acc_v, o);
    }
    float* red_t = &shV[0][0];   // 8 warps
    float* red_v = &shV[1][0];
    const int w = t >> 5, l = t & 31;
    if (l == 0) { red_t[w] = acc_t; red_v[w] = acc_v; }
    __syncthreads();
    if (t == 0) {
        float lt = 0.0f, lv = 0.0f;
#pragma unroll
        for (int k = 0; k < 8; ++k) { lt += red_t[k]; lv += red_v[k]; }
        // total = 0.25 * ((lt0+lt1) + (lv0+lv1))
        out[0] = 0.25f * (lt / (float)(B_ * NT_) + lv / (float)(B_ * NV_));
        // g_ticket already wrapped to 0 by atomicInc's modulus.
    }
}

extern "C" void kernel_launch(void* const* d_in, const int* in_sizes, int n_in,
                              void* d_out, int out_size) {
    const float* at0 = (const float*)d_in[0];
    const float* av0 = (const float*)d_in[1];
    const float* at1 = (const float*)d_in[2];
    const float* av1 = (const float*)d_in[3];

    // Single fused kernel: head-mean + diagonal row/col sums + last-block
    // scalar finalize.
    // grid: x = NV/32 = 18 j-tiles, y = NT/32 = 16 i-tiles, z = layer*8 + b
    dim3 grid(NV_ / 32, NT_ / 32, 2 * B_);
    diag_kernel<<<grid, 256>>>(at0, av0, at1, av1, (float*)d_out);
}

// round 6
// speedup vs baseline: 1.1398x; 1.1398x over previous
#include <cuda_runtime.h>

// Shapes fixed by the problem's setup_inputs().
#define B_  8
#define H_  16
#define NT_ 512
#define NV_ 576

#define EPS_MIN 1e-8f
#define EPS_MAX 1.0f

// Per-layer diagonal accumulators (atomic float adds).
// Zero-initialized at module load; finalize_kernel re-zeroes each element
// right after consuming it, so every kernel_launch call starts from zeros.
__device__ float g_tdiag[2 * B_ * NT_];   // 8192 floats = 32 * 256
__device__ float g_vdiag[2 * B_ * NV_];   // 9216 floats = 36 * 256

// One block (256 threads) = 32(i) x 32(j) tile for one (layer, b).
//   thread t: p = t & 7 (float4 slot), q = t >> 3 (row index 0..31)
//   attn_t: element (i = i0+q, j = j0+4p..+3)  -> float4 along j (contiguous)
//   attn_v: element (j = j0+q, i = i0+4p..+3)  -> float4 along i (contiguous)
// prod[i][j] = P_t_sum[i][j] * P_v_sum[j][i]; row sums -> g_tdiag,
// column sums -> g_vdiag. No fences, no tickets: kernel boundary orders
// everything before finalize_kernel.
__global__ __launch_bounds__(256)
void diag_kernel(const float* __restrict__ at0, const float* __restrict__ av0,
                 const float* __restrict__ at1, const float* __restrict__ av1,
                 float* __restrict__ out) {
    __shared__ float shV[32][33];   // P_v sums, stride-33 -> conflict-free transpose
    __shared__ float shP[32][33];   // prod tile for column reduction

    const int t = threadIdx.x;
    const int p = t & 7;            // float4 slot within row
    const int q = t >> 3;           // row (i for attn_t, j for attn_v)

    const int z     = blockIdx.z;
    const int layer = z >> 3;
    const int b     = z & 7;
    const int i0    = blockIdx.y * 32;
    const int j0    = blockIdx.x * 32;

    // Initialize the (poisoned) output once; ordered before finalize_kernel
    // by the kernel launch boundary.
    if (z == 0 && blockIdx.y == 0 && blockIdx.x == 0 && t == 0)
        out[0] = 0.0f;

    const float* __restrict__ at = layer ? at1 : at0;
    const float* __restrict__ av = layer ? av1 : av0;

    // Base pointers at h = 0; head stride in float4 units.
    const size_t hstride4 = (size_t)NT_ * NV_ / 4;   // 73728
    const float4* __restrict__ pt = (const float4*)(
        at + (((size_t)b * H_) * NT_ + (i0 + q)) * NV_ + (j0 + 4 * p));
    const float4* __restrict__ pv = (const float4*)(
        av + (((size_t)b * H_) * NV_ + (j0 + q)) * NT_ + (i0 + 4 * p));

    float4 st = make_float4(0.f, 0.f, 0.f, 0.f);
    float4 sv = make_float4(0.f, 0.f, 0.f, 0.f);
#pragma unroll
    for (int h = 0; h < H_; ++h) {
        const float4 a = pt[h * hstride4];
        const float4 v = pv[h * hstride4];
        st.x += a.x; st.y += a.y; st.z += a.z; st.w += a.w;
        sv.x += v.x; sv.y += v.y; sv.z += v.z; sv.w += v.w;
    }

    // Stage P_v sums: shV[j - j0][i - i0]
    shV[q][4 * p + 0] = sv.x;
    shV[q][4 * p + 1] = sv.y;
    shV[q][4 * p + 2] = sv.z;
    shV[q][4 * p + 3] = sv.w;
    __syncthreads();

    // prod for (i = i0+q, j = j0+4p+c): needs shV[4p+c][q] (conflict-free).
    const float pr0 = st.x * shV[4 * p + 0][q];
    const float pr1 = st.y * shV[4 * p + 1][q];
    const float pr2 = st.z * shV[4 * p + 2][q];
    const float pr3 = st.w * shV[4 * p + 3][q];

    // Row sum over j: reduce the 8 threads (p = 0..7) sharing row q.
    float rs = (pr0 + pr1) + (pr2 + pr3);
    rs += __shfl_xor_sync(0xffffffffu, rs, 1);
    rs += __shfl_xor_sync(0xffffffffu, rs, 2);
    rs += __shfl_xor_sync(0xffffffffu, rs, 4);
    if (p == 0)
        atomicAdd(&g_tdiag[layer * (B_ * NT_) + b * NT_ + i0 + q], rs);

    // Column sums: stage prod tile, then read transposed.
    shP[q][4 * p + 0] = pr0;
    shP[q][4 * p + 1] = pr1;
    shP[q][4 * p + 2] = pr2;
    shP[q][4 * p + 3] = pr3;
    __syncthreads();

    // Thread handles column j = j0+q, rows i = 4p+c (conflict-free reads).
    float cs = shP[4 * p + 0][q] + shP[4 * p + 1][q]
             + shP[4 * p + 2][q] + shP[4 * p + 3][q];
    cs += __shfl_xor_sync(0xffffffffu, cs, 1);
    cs += __shfl_xor_sync(0xffffffffu, cs, 2);
    cs += __shfl_xor_sync(0xffffffffu, cs, 4);
    if (p == 0)
        atomicAdd(&g_vdiag[layer * (B_ * NV_) + b * NV_ + j0 + q], cs);
}

// Finalize: exactly one diag element per thread.
//   blocks [0, 32)  -> g_tdiag (32*256 = 8192 elements)
//   blocks [32, 68) -> g_vdiag (36*256 = 9216 elements)
// Each thread: load (L2-coherent), re-zero, clip, -log, pre-scale; block
// reduce; one atomicAdd into out[0] per block. No fences/tickets needed:
// the kernel boundary ordered all diag atomics before us, and the harness's
// stream sync orders our atomics before the host reads d_out.
__global__ __launch_bounds__(256)
void finalize_kernel(float* __restrict__ out) {
    __shared__ float red[8];
    const int t   = threadIdx.x;
    const int blk = blockIdx.x;
    const float inv_h2 = 1.0f / (float)(H_ * H_);  // sums -> products of means

    float scale, d;
    if (blk < 32) {
        const int idx = blk * 256 + t;
        d = __ldcg(&g_tdiag[idx]) * inv_h2;
        __stcg(&g_tdiag[idx], 0.0f);               // reset for next replay
        scale = 0.25f / (float)(B_ * NT_);
    } else {
        const int idx = (blk - 32) * 256 + t;
        d = __ldcg(&g_vdiag[idx]) * inv_h2;
        __stcg(&g_vdiag[idx], 0.0f);
        scale = 0.25f / (float)(B_ * NV_);
    }
    d = fminf(fmaxf(d, EPS_MIN), EPS_MAX);
    float acc = -__logf(d) * scale;

#pragma unroll
    for (int o = 16; o > 0; o >>= 1)
        acc += __shfl_xor_sync(0xffffffffu, acc, o);
    const int w = t >> 5, l = t & 31;
    if (l == 0) red[w] = acc;
    __syncthreads();
    if (t == 0) {
        float s = 0.0f;
#pragma unroll
        for (int k = 0; k < 8; ++k) s += red[k];
        atomicAdd(out, s);
    }
}

extern "C" void kernel_launch(void* const* d_in, const int* in_sizes, int n_in,
                              void* d_out, int out_size) {
    const float* at0 = (const float*)d_in[0];
    const float* av0 = (const float*)d_in[1];
    const float* at1 = (const float*)d_in[2];
    const float* av1 = (const float*)d_in[3];

    // Fused head-mean + diagonal row/col sums (also zeroes out[0]).
    // grid: x = NV/32 = 18 j-tiles, y = NT/32 = 16 i-tiles, z = layer*8 + b
    dim3 grid(NV_ / 32, NT_ / 32, 2 * B_);
    diag_kernel<<<grid, 256>>>(at0, av0, at1, av1, (float*)d_out);

    // One element per thread; one atomicAdd into out[0] per block.
    finalize_kernel<<<68, 256>>>((float*)d_out);
}